// round 1
// baseline (speedup 1.0000x reference)
#include <cuda_runtime.h>
#include <cuda_bf16.h>
#include <math.h>

// Problem dims (fixed)
#define B   2
#define N0  1536
#define N1  512
#define NTOT 2048      // N0 + N1
#define D0  1024
#define D1  512
#define H   16
#define DH  64
#define DI  1024       // H*DH
#define SOFTCLAMP 50.0f

// ---------------------------------------------------------------------------
// Scratch (device globals; no allocation allowed)
// ---------------------------------------------------------------------------
__device__ float g_qkv0[(size_t)B * N0 * 3 * DI];   // [3072, 3072]
__device__ float g_qkv1[(size_t)B * N1 * 3 * DI];   // [1024, 3072]
__device__ float g_q[(size_t)B * H * NTOT * DH];    // [b,h,N,d]
__device__ float g_k[(size_t)B * H * NTOT * DH];
__device__ float g_v[(size_t)B * H * NTOT * DH];
__device__ float g_o[(size_t)B * NTOT * DI];        // [b,N,h*d] merged heads

// ---------------------------------------------------------------------------
// SGEMM: C[M,N] = A[M,K] @ B[K,N], row-major, all dims % 64 == 0, K % 16 == 0
// 64x64 tile, BK=16, 256 threads, 4x4 per thread
// ---------------------------------------------------------------------------
__global__ __launch_bounds__(256) void sgemm64(
    const float* __restrict__ A, const float* __restrict__ Bm,
    float* __restrict__ C, int M, int N, int K)
{
    __shared__ float As[16][68];   // [k][m], padded (stride % 32 == 4)
    __shared__ float Bs[16][68];   // [k][n]

    int tid = threadIdx.x;
    int tx = tid & 15;             // col group
    int ty = tid >> 4;             // row group
    int row0 = blockIdx.y * 64;
    int col0 = blockIdx.x * 64;

    int ar  = tid >> 2;            // 0..63
    int ak4 = (tid & 3) << 2;      // 0,4,8,12
    int bk  = tid >> 4;            // 0..15
    int bc4 = (tid & 15) << 2;     // 0..60

    float acc[4][4] = {};

    for (int k0 = 0; k0 < K; k0 += 16) {
        float4 a = *(const float4*)(A + (size_t)(row0 + ar) * K + k0 + ak4);
        As[ak4 + 0][ar] = a.x;
        As[ak4 + 1][ar] = a.y;
        As[ak4 + 2][ar] = a.z;
        As[ak4 + 3][ar] = a.w;
        float4 b = *(const float4*)(Bm + (size_t)(k0 + bk) * N + col0 + bc4);
        *(float4*)&Bs[bk][bc4] = b;
        __syncthreads();

        #pragma unroll
        for (int k = 0; k < 16; k++) {
            float4 av = *(float4*)&As[k][ty << 2];
            float4 bv = *(float4*)&Bs[k][tx << 2];
            float avv[4] = {av.x, av.y, av.z, av.w};
            float bvv[4] = {bv.x, bv.y, bv.z, bv.w};
            #pragma unroll
            for (int i = 0; i < 4; i++)
                #pragma unroll
                for (int j = 0; j < 4; j++)
                    acc[i][j] += avv[i] * bvv[j];
        }
        __syncthreads();
    }

    #pragma unroll
    for (int i = 0; i < 4; i++) {
        float4 r = make_float4(acc[i][0], acc[i][1], acc[i][2], acc[i][3]);
        *(float4*)(C + (size_t)(row0 + (ty << 2) + i) * N + col0 + (tx << 2)) = r;
    }
}

// ---------------------------------------------------------------------------
// QKV transform: per (b,n,h) warp — RMSNorm q,k; scatter q/k/v to [b,h,N,d]
// ---------------------------------------------------------------------------
__global__ __launch_bounds__(256) void qkv_transform(
    const float* __restrict__ qg0, const float* __restrict__ kg0,
    const float* __restrict__ qg1, const float* __restrict__ kg1)
{
    int gw   = (blockIdx.x * blockDim.x + threadIdx.x) >> 5;  // global warp
    int lane = threadIdx.x & 31;
    // gw = ((b*NTOT + n)*H + h)
    int h  = gw & (H - 1);
    int bn = gw >> 4;
    int n  = bn & (NTOT - 1);
    int b  = bn >> 11;

    const float* src;
    const float *qg, *kg;
    size_t rowoff;
    if (n < N0) { src = g_qkv0; rowoff = (size_t)(b * N0 + n) * (3 * DI); qg = qg0; kg = kg0; }
    else        { src = g_qkv1; rowoff = (size_t)(b * N1 + (n - N0)) * (3 * DI); qg = qg1; kg = kg1; }

    const float* qp = src + rowoff + h * DH;
    const float* kp = qp + DI;
    const float* vp = qp + 2 * DI;

    float q0 = qp[lane], q1 = qp[lane + 32];
    float k0 = kp[lane], k1 = kp[lane + 32];
    float v0 = vp[lane], v1 = vp[lane + 32];

    float qs = q0 * q0 + q1 * q1;
    float ks = k0 * k0 + k1 * k1;
    #pragma unroll
    for (int off = 16; off; off >>= 1) {
        qs += __shfl_xor_sync(0xFFFFFFFFu, qs, off);
        ks += __shfl_xor_sync(0xFFFFFFFFu, ks, off);
    }
    float qinv = 8.0f / fmaxf(sqrtf(qs), 1e-12f);   // sqrt(DH)=8
    float kinv = 8.0f / fmaxf(sqrtf(ks), 1e-12f);

    size_t dst = ((size_t)(b * H + h) * NTOT + n) * DH;
    float gq0 = qg[h * DH + lane], gq1 = qg[h * DH + lane + 32];
    float gk0 = kg[h * DH + lane], gk1 = kg[h * DH + lane + 32];
    g_q[dst + lane]      = q0 * qinv * gq0;
    g_q[dst + lane + 32] = q1 * qinv * gq1;
    g_k[dst + lane]      = k0 * kinv * gk0;
    g_k[dst + lane + 32] = k1 * kinv * gk1;
    g_v[dst + lane]      = v0;
    g_v[dst + lane + 32] = v1;
}

// ---------------------------------------------------------------------------
// Attention: one block = 32 queries of one (b,h). One-pass exp (tanh clamp
// bounds logits to [-50,50] so exp can't overflow fp32 — no running max).
// ---------------------------------------------------------------------------
__global__ __launch_bounds__(256) void attention_kernel()
{
    __shared__ float Qs[32][68];   // stride%32==4 -> conflict-free float4 by row
    __shared__ float Ks[32][64];   // broadcast reads, no pad needed
    __shared__ float Vs[32][64];
    __shared__ float Ps[32][33];   // scalar reads, odd stride
    __shared__ float rsum[32];

    int bh  = blockIdx.y;                  // 0..31 (b*H+h)
    int q0i = blockIdx.x * 32;
    int tid = threadIdx.x;
    size_t base = (size_t)bh * NTOT * DH;

    // load Q tile: 32x64
    #pragma unroll
    for (int i = 0; i < 8; i++) {
        int idx = tid + i * 256;
        int r = idx >> 6, c = idx & 63;
        Qs[r][c] = g_q[base + (size_t)(q0i + r) * DH + c];
    }

    int qi = tid & 31;
    int grp = tid >> 5;                    // 0..7
    float acc[8] = {};
    float rs = 0.0f;

    for (int kc = 0; kc < NTOT / 32; kc++) {
        // load K,V chunk 32x64 each
        #pragma unroll
        for (int i = 0; i < 8; i++) {
            int idx = tid + i * 256;
            int r = idx >> 6, c = idx & 63;
            size_t g = base + (size_t)(kc * 32 + r) * DH + c;
            Ks[r][c] = g_k[g];
            Vs[r][c] = g_v[g];
        }
        __syncthreads();

        // scores: each thread -> (qi, 4 keys)
        float s[4] = {};
        #pragma unroll
        for (int kk = 0; kk < 16; kk++) {
            float4 qv = *(float4*)&Qs[qi][kk << 2];
            #pragma unroll
            for (int jj = 0; jj < 4; jj++) {
                float4 kv = *(float4*)&Ks[(grp << 2) + jj][kk << 2];
                s[jj] += qv.x * kv.x + qv.y * kv.y + qv.z * kv.z + qv.w * kv.w;
            }
        }
        #pragma unroll
        for (int jj = 0; jj < 4; jj++) {
            float sc = s[jj] * 0.125f;                       // D^-0.5
            sc = tanhf(sc * (1.0f / SOFTCLAMP)) * SOFTCLAMP; // softclamp
            Ps[qi][(grp << 2) + jj] = __expf(sc);
        }
        __syncthreads();

        // o accumulation: thread -> (qi, 8 d-columns)
        int d0 = grp << 3;
        #pragma unroll
        for (int j = 0; j < 32; j++) {
            float p = Ps[qi][j];
            float4 v1 = *(float4*)&Vs[j][d0];
            float4 v2 = *(float4*)&Vs[j][d0 + 4];
            acc[0] += p * v1.x; acc[1] += p * v1.y;
            acc[2] += p * v1.z; acc[3] += p * v1.w;
            acc[4] += p * v2.x; acc[5] += p * v2.y;
            acc[6] += p * v2.z; acc[7] += p * v2.w;
            if (grp == 0) rs += p;
        }
        __syncthreads();
    }

    if (grp == 0) rsum[qi] = rs;
    __syncthreads();
    float inv = 1.0f / rsum[qi];

    int b = bh >> 4, h = bh & (H - 1);
    size_t o_off = ((size_t)(b * NTOT + q0i + qi) * DI) + h * DH + (grp << 3);
    float4 r1 = make_float4(acc[0] * inv, acc[1] * inv, acc[2] * inv, acc[3] * inv);
    float4 r2 = make_float4(acc[4] * inv, acc[5] * inv, acc[6] * inv, acc[7] * inv);
    *(float4*)&g_o[o_off]     = r1;
    *(float4*)&g_o[o_off + 4] = r2;
}

// ---------------------------------------------------------------------------
// Launch
// ---------------------------------------------------------------------------
extern "C" void kernel_launch(void* const* d_in, const int* in_sizes, int n_in,
                              void* d_out, int out_size)
{
    const float* x0    = (const float*)d_in[0];
    const float* x1    = (const float*)d_in[1];
    const float* Wqkv0 = (const float*)d_in[2];
    const float* Wqkv1 = (const float*)d_in[3];
    const float* qg0   = (const float*)d_in[4];
    const float* kg0   = (const float*)d_in[5];
    const float* qg1   = (const float*)d_in[6];
    const float* kg1   = (const float*)d_in[7];
    const float* Wout0 = (const float*)d_in[8];
    const float* Wout1 = (const float*)d_in[9];
    float* out = (float*)d_out;

    float *qkv0, *qkv1, *o;
    cudaGetSymbolAddress((void**)&qkv0, g_qkv0);
    cudaGetSymbolAddress((void**)&qkv1, g_qkv1);
    cudaGetSymbolAddress((void**)&o,    g_o);

    dim3 blk(256);

    // QKV projections
    sgemm64<<<dim3(3 * DI / 64, B * N0 / 64), blk>>>(x0, Wqkv0, qkv0, B * N0, 3 * DI, D0);
    sgemm64<<<dim3(3 * DI / 64, B * N1 / 64), blk>>>(x1, Wqkv1, qkv1, B * N1, 3 * DI, D1);

    // RMSNorm + layout to [b,h,N,d]
    qkv_transform<<<(B * NTOT * H) / 8, 256>>>(qg0, kg0, qg1, kg1);

    // Attention
    attention_kernel<<<dim3(NTOT / 32, B * H), 256>>>();

    // Output projections (per batch; rows of each modality are contiguous)
    float* out1 = out + (size_t)B * N0 * D0;
    for (int b = 0; b < B; b++) {
        sgemm64<<<dim3(D0 / 64, N0 / 64), blk>>>(
            o + (size_t)b * NTOT * DI, Wout0,
            out + (size_t)b * N0 * D0, N0, D0, DI);
        sgemm64<<<dim3(D1 / 64, N1 / 64), blk>>>(
            o + ((size_t)b * NTOT + N0) * DI, Wout1,
            out1 + (size_t)b * N1 * D1, N1, D1, DI);
    }
}

// round 4
// speedup vs baseline: 3.1056x; 3.1056x over previous
#include <cuda_runtime.h>
#include <math.h>
#include <stdint.h>

#define B   2
#define N0  1536
#define N1  512
#define NTOT 2048
#define D0  1024
#define D1  512
#define H   16
#define DH  64
#define DI  1024

// ---------------- scratch ----------------
__device__ float g_qkv0[(size_t)B * N0 * 3 * DI];
__device__ float g_qkv1[(size_t)B * N1 * 3 * DI];
__device__ float g_q[(size_t)B * H * NTOT * DH];
__device__ float g_k[(size_t)B * H * NTOT * DH];
__device__ float g_v[(size_t)B * H * NTOT * DH];
__device__ float g_o[(size_t)B * NTOT * DI];
__device__ float g_wt0[(size_t)3 * DI * D0];
__device__ float g_wt1[(size_t)3 * DI * D1];
__device__ float g_wtO0[(size_t)D0 * DI];
__device__ float g_wtO1[(size_t)D1 * DI];

// ---------------- helpers ----------------
__device__ __forceinline__ uint32_t cvt_tf32(float x) {
    uint32_t r; asm("cvt.rna.tf32.f32 %0, %1;" : "=r"(r) : "f"(x)); return r;
}
__device__ __forceinline__ float tf(float x) { return __uint_as_float(cvt_tf32(x)); }
__device__ __forceinline__ float ex2f(float x) {
    float r; asm("ex2.approx.ftz.f32 %0, %1;" : "=f"(r) : "f"(x)); return r;
}
__device__ __forceinline__ void mma8(float (&d)[4], const uint32_t* a, const uint32_t* b) {
    asm volatile("mma.sync.aligned.m16n8k8.row.col.f32.tf32.tf32.f32 "
        "{%0,%1,%2,%3}, {%4,%5,%6,%7}, {%8,%9}, {%0,%1,%2,%3};"
        : "+f"(d[0]), "+f"(d[1]), "+f"(d[2]), "+f"(d[3])
        : "r"(a[0]), "r"(a[1]), "r"(a[2]), "r"(a[3]), "r"(b[0]), "r"(b[1]));
}

// ---------------------------------------------------------------------------
// Transpose: out[n][k] = in[k][n]
// ---------------------------------------------------------------------------
__global__ void transpose_k(const float* __restrict__ in, float* __restrict__ out, int K, int N) {
    __shared__ float t[32][33];
    int k0 = blockIdx.y * 32, n0 = blockIdx.x * 32;
    #pragma unroll
    for (int i = threadIdx.y; i < 32; i += 8)
        t[i][threadIdx.x] = in[(size_t)(k0 + i) * N + n0 + threadIdx.x];
    __syncthreads();
    #pragma unroll
    for (int i = threadIdx.y; i < 32; i += 8)
        out[(size_t)(n0 + i) * K + k0 + threadIdx.x] = t[threadIdx.x][i];
}

// ---------------------------------------------------------------------------
// tf32 mma.sync GEMM: C[M,N] = A[M,K] * Bt[N,K]^T (both K-major).
// 128x128 tile, BK=32. 8 warps: warp (wm,wn) -> 64x32 warp tile.
// ---------------------------------------------------------------------------
#define GSTR 36
#define GEMM_SMEM (2 * 128 * GSTR * 4)

__global__ __launch_bounds__(256) void mma_gemm(
    const float* __restrict__ A, const float* __restrict__ Bt,
    float* __restrict__ C, int M, int N, int K)
{
    extern __shared__ float sm[];
    float* As = sm;                 // [128][36]
    float* Bs = sm + 128 * GSTR;    // [128][36]
    int tid = threadIdx.x, lane = tid & 31, wid = tid >> 5;
    int wm = wid & 1, wn = wid >> 1;
    int row0 = blockIdx.y * 128, col0 = blockIdx.x * 128;
    int r = lane >> 2, c = lane & 3;

    float acc[4][4][4] = {};

    for (int t = 0; t < K; t += 32) {
        __syncthreads();
        #pragma unroll
        for (int i = 0; i < 4; i++) {
            int chunk = tid + i * 256;
            int rr = chunk >> 3, c4 = (chunk & 7) << 2;
            float4 va = *(const float4*)(A + (size_t)(row0 + rr) * K + t + c4);
            float4 vb = *(const float4*)(Bt + (size_t)(col0 + rr) * K + t + c4);
            *(float4*)&As[rr * GSTR + c4] = make_float4(tf(va.x), tf(va.y), tf(va.z), tf(va.w));
            *(float4*)&Bs[rr * GSTR + c4] = make_float4(tf(vb.x), tf(vb.y), tf(vb.z), tf(vb.w));
        }
        __syncthreads();

        #pragma unroll
        for (int ks = 0; ks < 4; ks++) {
            uint32_t af[4][4], bf[4][2];
            #pragma unroll
            for (int mi = 0; mi < 4; mi++) {
                const float* p = &As[(wm * 64 + mi * 16 + r) * GSTR + ks * 8 + c];
                af[mi][0] = __float_as_uint(p[0]);
                af[mi][1] = __float_as_uint(p[8 * GSTR]);
                af[mi][2] = __float_as_uint(p[4]);
                af[mi][3] = __float_as_uint(p[8 * GSTR + 4]);
            }
            #pragma unroll
            for (int ni = 0; ni < 4; ni++) {
                const float* p = &Bs[(wn * 32 + ni * 8 + r) * GSTR + ks * 8 + c];
                bf[ni][0] = __float_as_uint(p[0]);
                bf[ni][1] = __float_as_uint(p[4]);
            }
            #pragma unroll
            for (int mi = 0; mi < 4; mi++)
                #pragma unroll
                for (int ni = 0; ni < 4; ni++)
                    mma8(acc[mi][ni], af[mi], bf[ni]);
        }
    }

    #pragma unroll
    for (int mi = 0; mi < 4; mi++) {
        int row = row0 + wm * 64 + mi * 16 + r;
        #pragma unroll
        for (int ni = 0; ni < 4; ni++) {
            int col = col0 + wn * 32 + ni * 8 + 2 * c;
            *(float2*)&C[(size_t)row * N + col] = make_float2(acc[mi][ni][0], acc[mi][ni][1]);
            *(float2*)&C[(size_t)(row + 8) * N + col] = make_float2(acc[mi][ni][2], acc[mi][ni][3]);
        }
    }
}

// ---------------------------------------------------------------------------
// QKV transform: RMSNorm q (D^-0.5 folded), k; scatter to [b,h,N,d]
// ---------------------------------------------------------------------------
__global__ __launch_bounds__(256) void qkv_transform(
    const float* __restrict__ qg0, const float* __restrict__ kg0,
    const float* __restrict__ qg1, const float* __restrict__ kg1)
{
    int gw = (blockIdx.x * blockDim.x + threadIdx.x) >> 5;
    int lane = threadIdx.x & 31;
    int h = gw & (H - 1);
    int bn = gw >> 4;
    int n = bn & (NTOT - 1);
    int b = bn >> 11;

    const float *src, *qg, *kg;
    size_t rowoff;
    if (n < N0) { src = g_qkv0; rowoff = (size_t)(b * N0 + n) * (3 * DI); qg = qg0; kg = kg0; }
    else        { src = g_qkv1; rowoff = (size_t)(b * N1 + (n - N0)) * (3 * DI); qg = qg1; kg = kg1; }

    const float* qp = src + rowoff + h * DH;
    const float* kp = qp + DI;
    const float* vp = qp + 2 * DI;
    float q0 = qp[lane], q1 = qp[lane + 32];
    float k0 = kp[lane], k1 = kp[lane + 32];
    float v0 = vp[lane], v1 = vp[lane + 32];

    float qs = q0 * q0 + q1 * q1, ks = k0 * k0 + k1 * k1;
    #pragma unroll
    for (int off = 16; off; off >>= 1) {
        qs += __shfl_xor_sync(0xFFFFFFFFu, qs, off);
        ks += __shfl_xor_sync(0xFFFFFFFFu, ks, off);
    }
    float qinv = 1.0f / fmaxf(sqrtf(qs), 1e-12f);   // 8 (rmsnorm) * 0.125 (scale) = 1
    float kinv = 8.0f / fmaxf(sqrtf(ks), 1e-12f);

    size_t dst = ((size_t)(b * H + h) * NTOT + n) * DH;
    g_q[dst + lane]      = q0 * qinv * qg[h * DH + lane];
    g_q[dst + lane + 32] = q1 * qinv * qg[h * DH + lane + 32];
    g_k[dst + lane]      = k0 * kinv * kg[h * DH + lane];
    g_k[dst + lane + 32] = k1 * kinv * kg[h * DH + lane + 32];
    g_v[dst + lane]      = v0;
    g_v[dst + lane + 32] = v1;
}

// ---------------------------------------------------------------------------
// Attention (mma.sync flash). CTA = 128 queries x one (b,h); 256 thr, 8 warps
// (16 q each); 32 key chunks of 64. Bounded logits -> no running max.
// ---------------------------------------------------------------------------
#define ASTR 68
#define SQ 0
#define SK (128 * ASTR)            // 8704
#define SV (SK + 64 * ASTR)        // 13056
#define SP (SV + 64 * ASTR)        // 17408
#define ATT_SMEM ((SP + 128 * ASTR) * 4)   // 104448 B

__global__ __launch_bounds__(256) void attention_mma()
{
    extern __shared__ float sm[];
    int tid = threadIdx.x, lane = tid & 31, wid = tid >> 5;
    int wq = wid * 16;
    int bh = blockIdx.y;
    int q0 = blockIdx.x * 128;
    size_t base = (size_t)bh * NTOT * DH;
    int r = lane >> 2, c = lane & 3;

    // Q tile -> smem (tf32), once
    const float* Qg = g_q + base + (size_t)q0 * DH;
    #pragma unroll
    for (int i = 0; i < 8; i++) {
        int chunk = tid + i * 256;
        int row = chunk >> 4, c4 = (chunk & 15) << 2;
        float4 v = *(const float4*)(Qg + row * 64 + c4);
        *(float4*)&sm[SQ + row * ASTR + c4] = make_float4(tf(v.x), tf(v.y), tf(v.z), tf(v.w));
    }

    const float C1 = 72.134752f, C2 = -24.0449173f, C3 = 9.6179669f; // 50*log2e*{1,-1/3,2/15}
    float oacc[8][4] = {};
    float rs0 = 0.0f, rs1 = 0.0f;

    for (int kc = 0; kc < 32; kc++) {
        const float* Kg = g_k + base + (size_t)(kc * 64) * DH;
        const float* Vg = g_v + base + (size_t)(kc * 64) * DH;
        __syncthreads();                       // prior consumers done (covers Q on kc=0)
        #pragma unroll
        for (int i = 0; i < 4; i++) {          // K: direct [key][d]
            int chunk = tid + i * 256;
            int row = chunk >> 4, c4 = (chunk & 15) << 2;
            float4 v = *(const float4*)(Kg + row * 64 + c4);
            *(float4*)&sm[SK + row * ASTR + c4] = make_float4(tf(v.x), tf(v.y), tf(v.z), tf(v.w));
        }
        #pragma unroll
        for (int i = 0; i < 4; i++) {          // V: transposed [d][key]
            int chunk = i * 256 + tid;
            int key = chunk & 63, d4 = chunk >> 6;
            float4 v = *(const float4*)(Vg + key * 64 + d4 * 4);
            sm[SV + (d4 * 4 + 0) * ASTR + key] = tf(v.x);
            sm[SV + (d4 * 4 + 1) * ASTR + key] = tf(v.y);
            sm[SV + (d4 * 4 + 2) * ASTR + key] = tf(v.z);
            sm[SV + (d4 * 4 + 3) * ASTR + key] = tf(v.w);
        }
        __syncthreads();

        // S = Q K^T (16q x 64keys per warp)
        float sacc[8][4] = {};
        #pragma unroll
        for (int ks = 0; ks < 8; ks++) {
            uint32_t af[4];
            const float* pa = &sm[SQ + (wq + r) * ASTR + ks * 8 + c];
            af[0] = __float_as_uint(pa[0]);
            af[1] = __float_as_uint(pa[8 * ASTR]);
            af[2] = __float_as_uint(pa[4]);
            af[3] = __float_as_uint(pa[8 * ASTR + 4]);
            #pragma unroll
            for (int ni = 0; ni < 8; ni++) {
                uint32_t bf[2];
                const float* pb = &sm[SK + (ni * 8 + r) * ASTR + ks * 8 + c];
                bf[0] = __float_as_uint(pb[0]);
                bf[1] = __float_as_uint(pb[4]);
                mma8(sacc[ni], af, bf);
            }
        }

        // softmax (softclamp poly + exp2), write P to per-warp smem region
        #pragma unroll
        for (int ni = 0; ni < 8; ni++) {
            float p[4];
            #pragma unroll
            for (int j = 0; j < 4; j++) {
                float x = sacc[ni][j] * 0.02f;
                float x2 = x * x;
                float u = x * fmaf(x2, fmaf(x2, C3, C2), C1);
                p[j] = ex2f(u);
            }
            rs0 += p[0] + p[1];
            rs1 += p[2] + p[3];
            *(float2*)&sm[SP + (wq + r) * ASTR + ni * 8 + 2 * c]     = make_float2(tf(p[0]), tf(p[1]));
            *(float2*)&sm[SP + (wq + r + 8) * ASTR + ni * 8 + 2 * c] = make_float2(tf(p[2]), tf(p[3]));
        }
        __syncwarp();

        // O += P V
        #pragma unroll
        for (int ks = 0; ks < 8; ks++) {
            uint32_t af[4];
            const float* pa = &sm[SP + (wq + r) * ASTR + ks * 8 + c];
            af[0] = __float_as_uint(pa[0]);
            af[1] = __float_as_uint(pa[8 * ASTR]);
            af[2] = __float_as_uint(pa[4]);
            af[3] = __float_as_uint(pa[8 * ASTR + 4]);
            #pragma unroll
            for (int ni = 0; ni < 8; ni++) {
                uint32_t bf[2];
                const float* pb = &sm[SV + (ni * 8 + r) * ASTR + ks * 8 + c];
                bf[0] = __float_as_uint(pb[0]);
                bf[1] = __float_as_uint(pb[4]);
                mma8(oacc[ni], af, bf);
            }
        }
    }

    // normalize + write
    rs0 += __shfl_xor_sync(0xFFFFFFFFu, rs0, 1);
    rs0 += __shfl_xor_sync(0xFFFFFFFFu, rs0, 2);
    rs1 += __shfl_xor_sync(0xFFFFFFFFu, rs1, 1);
    rs1 += __shfl_xor_sync(0xFFFFFFFFu, rs1, 2);
    float i0 = 1.0f / rs0, i1 = 1.0f / rs1;

    int b = bh >> 4, h = bh & (H - 1);
    int row = q0 + wq + r;
    float* op  = g_o + (size_t)(b * NTOT + row) * DI + h * DH;
    float* op8 = op + (size_t)8 * DI;
    #pragma unroll
    for (int ni = 0; ni < 8; ni++) {
        int col = ni * 8 + 2 * c;
        *(float2*)&op[col]  = make_float2(oacc[ni][0] * i0, oacc[ni][1] * i0);
        *(float2*)&op8[col] = make_float2(oacc[ni][2] * i1, oacc[ni][3] * i1);
    }
}

// ---------------------------------------------------------------------------
extern "C" void kernel_launch(void* const* d_in, const int* in_sizes, int n_in,
                              void* d_out, int out_size)
{
    const float* x0    = (const float*)d_in[0];
    const float* x1    = (const float*)d_in[1];
    const float* Wqkv0 = (const float*)d_in[2];
    const float* Wqkv1 = (const float*)d_in[3];
    const float* qg0   = (const float*)d_in[4];
    const float* kg0   = (const float*)d_in[5];
    const float* qg1   = (const float*)d_in[6];
    const float* kg1   = (const float*)d_in[7];
    const float* Wout0 = (const float*)d_in[8];
    const float* Wout1 = (const float*)d_in[9];
    float* out = (float*)d_out;

    float *qkv0, *qkv1, *o, *wt0, *wt1, *wtO0, *wtO1;
    cudaGetSymbolAddress((void**)&qkv0, g_qkv0);
    cudaGetSymbolAddress((void**)&qkv1, g_qkv1);
    cudaGetSymbolAddress((void**)&o,    g_o);
    cudaGetSymbolAddress((void**)&wt0,  g_wt0);
    cudaGetSymbolAddress((void**)&wt1,  g_wt1);
    cudaGetSymbolAddress((void**)&wtO0, g_wtO0);
    cudaGetSymbolAddress((void**)&wtO1, g_wtO1);

    cudaFuncSetAttribute(attention_mma, cudaFuncAttributeMaxDynamicSharedMemorySize, ATT_SMEM);

    dim3 t8(32, 8);
    transpose_k<<<dim3(3 * DI / 32, D0 / 32), t8>>>(Wqkv0, wt0, D0, 3 * DI);
    transpose_k<<<dim3(3 * DI / 32, D1 / 32), t8>>>(Wqkv1, wt1, D1, 3 * DI);
    transpose_k<<<dim3(D0 / 32, DI / 32), t8>>>(Wout0, wtO0, DI, D0);
    transpose_k<<<dim3(D1 / 32, DI / 32), t8>>>(Wout1, wtO1, DI, D1);

    mma_gemm<<<dim3(3 * DI / 128, B * N0 / 128), 256, GEMM_SMEM>>>(x0, wt0, qkv0, B * N0, 3 * DI, D0);
    mma_gemm<<<dim3(3 * DI / 128, B * N1 / 128), 256, GEMM_SMEM>>>(x1, wt1, qkv1, B * N1, 3 * DI, D1);

    qkv_transform<<<(B * NTOT * H) / 8, 256>>>(qg0, kg0, qg1, kg1);

    attention_mma<<<dim3(NTOT / 128, B * H), 256, ATT_SMEM>>>();

    float* out1 = out + (size_t)B * N0 * D0;
    for (int b = 0; b < B; b++) {
        mma_gemm<<<dim3(D0 / 128, N0 / 128), 256, GEMM_SMEM>>>(
            o + (size_t)b * NTOT * DI, wtO0, out + (size_t)b * N0 * D0, N0, D0, DI);
        mma_gemm<<<dim3(D1 / 128, N1 / 128), 256, GEMM_SMEM>>>(
            o + ((size_t)b * NTOT + N0) * DI, wtO1, out1 + (size_t)b * N1 * D1, N1, D1, DI);
    }
}

// round 6
// speedup vs baseline: 3.5432x; 1.1409x over previous
#include <cuda_runtime.h>
#include <math.h>
#include <stdint.h>

#define B   2
#define N0  1536
#define N1  512
#define NTOT 2048
#define D0  1024
#define D1  512
#define H   16
#define DH  64
#define DI  1024

// ---------------- scratch ----------------
__device__ float g_qkv0[(size_t)B * N0 * 3 * DI];
__device__ float g_qkv1[(size_t)B * N1 * 3 * DI];
__device__ float g_q[(size_t)B * H * NTOT * DH];
__device__ float g_k[(size_t)B * H * NTOT * DH];
__device__ float g_v[(size_t)B * H * NTOT * DH];
__device__ float g_vt[(size_t)B * H * DH * NTOT];   // V^T per (b,h): [d][n]
__device__ float g_o[(size_t)B * NTOT * DI];
__device__ float g_wt0[(size_t)3 * DI * D0];
__device__ float g_wt1[(size_t)3 * DI * D1];
__device__ float g_wtO0[(size_t)D0 * DI];
__device__ float g_wtO1[(size_t)D1 * DI];
__device__ float g_x0r[(size_t)B * N0 * D0];
__device__ float g_x1r[(size_t)B * N1 * D1];

// ---------------- helpers ----------------
__device__ __forceinline__ uint32_t smem_u32(const void* p) {
    uint32_t a;
    asm("{ .reg .u64 t; cvta.to.shared.u64 t, %1; cvt.u32.u64 %0, t; }" : "=r"(a) : "l"(p));
    return a;
}
__device__ __forceinline__ uint32_t cvt_tf32(float x) {
    uint32_t r; asm("cvt.rna.tf32.f32 %0, %1;" : "=r"(r) : "f"(x)); return r;
}
__device__ __forceinline__ float tf(float x) { return __uint_as_float(cvt_tf32(x)); }
__device__ __forceinline__ float ex2f(float x) {
    float r; asm("ex2.approx.ftz.f32 %0, %1;" : "=f"(r) : "f"(x)); return r;
}
__device__ __forceinline__ void mma8(float (&d)[4], const uint32_t* a, const uint32_t* b) {
    asm volatile("mma.sync.aligned.m16n8k8.row.col.f32.tf32.tf32.f32 "
        "{%0,%1,%2,%3}, {%4,%5,%6,%7}, {%8,%9}, {%0,%1,%2,%3};"
        : "+f"(d[0]), "+f"(d[1]), "+f"(d[2]), "+f"(d[3])
        : "r"(a[0]), "r"(a[1]), "r"(a[2]), "r"(a[3]), "r"(b[0]), "r"(b[1]));
}
__device__ __forceinline__ void cpa16(uint32_t dst, const void* src) {
    asm volatile("cp.async.cg.shared.global [%0], [%1], 16;" :: "r"(dst), "l"(src));
}
#define CP_COMMIT() asm volatile("cp.async.commit_group;" ::: "memory")
#define CP_WAIT1()  asm volatile("cp.async.wait_group 1;" ::: "memory")
#define CP_WAIT0()  asm volatile("cp.async.wait_group 0;" ::: "memory")

// ---------------------------------------------------------------------------
// Elementwise tf32 rounding
// ---------------------------------------------------------------------------
__global__ void round_tf(const float* __restrict__ in, float* __restrict__ out) {
    size_t i = ((size_t)blockIdx.x * 256 + threadIdx.x) * 4;
    float4 v = *(const float4*)(in + i);
    *(float4*)(out + i) = make_float4(tf(v.x), tf(v.y), tf(v.z), tf(v.w));
}

// ---------------------------------------------------------------------------
// Weight transpose + round: out[n][k] = tf(in[k][n])
// ---------------------------------------------------------------------------
__global__ void transpose_k(const float* __restrict__ in, float* __restrict__ out, int K, int N) {
    __shared__ float t[32][33];
    int k0 = blockIdx.y * 32, n0 = blockIdx.x * 32;
    #pragma unroll
    for (int i = threadIdx.y; i < 32; i += 8)
        t[i][threadIdx.x] = in[(size_t)(k0 + i) * N + n0 + threadIdx.x];
    __syncthreads();
    #pragma unroll
    for (int i = threadIdx.y; i < 32; i += 8)
        out[(size_t)(n0 + i) * K + k0 + threadIdx.x] = tf(t[threadIdx.x][i]);
}

// ---------------------------------------------------------------------------
// V transpose per (b,h): g_v [n][d] -> g_vt [d][n]  (values already rounded)
// ---------------------------------------------------------------------------
__global__ void transpose_v() {
    __shared__ float t[32][33];
    int bh = blockIdx.z;
    const float* in = g_v + (size_t)bh * NTOT * DH;
    float* out = g_vt + (size_t)bh * DH * NTOT;
    int d0 = blockIdx.x * 32, n0 = blockIdx.y * 32;
    #pragma unroll
    for (int i = threadIdx.y; i < 32; i += 8)
        t[i][threadIdx.x] = in[(size_t)(n0 + i) * DH + d0 + threadIdx.x];
    __syncthreads();
    #pragma unroll
    for (int i = threadIdx.y; i < 32; i += 8)
        out[(size_t)(d0 + i) * NTOT + n0 + threadIdx.x] = t[threadIdx.x][i];
}

// ---------------------------------------------------------------------------
// tf32 mma.sync GEMM, cp.async 2-stage: C[M,N] = A[M,K] * Bt[N,K]^T
// 128x128 tile, BK=32, 8 warps (64x32 each). Operands pre-rounded to tf32.
// ---------------------------------------------------------------------------
#define GSTR 36
#define GST (128 * GSTR)                  // floats per stage buffer
#define GEMM_SMEM (4 * GST * 4)           // 73728 B

__global__ __launch_bounds__(256) void mma_gemm(
    const float* __restrict__ A, const float* __restrict__ Bt,
    float* __restrict__ C, int M, int N, int K)
{
    extern __shared__ float sm[];
    uint32_t sbase = smem_u32(sm);
    int tid = threadIdx.x, lane = tid & 31, wid = tid >> 5;
    int wm = wid & 1, wn = wid >> 1;
    int row0 = blockIdx.y * 128, col0 = blockIdx.x * 128;
    int r = lane >> 2, c = lane & 3;
    int lr = tid >> 3, lc = (tid & 7) << 2;
    int KT = K >> 5;

    auto issue = [&](int t, int s) {
        const float* ap = A + (size_t)(row0 + lr) * K + t * 32 + lc;
        const float* bp = Bt + (size_t)(col0 + lr) * K + t * 32 + lc;
        uint32_t da = sbase + (uint32_t)(s * GST + lr * GSTR + lc) * 4u;
        uint32_t db = sbase + (uint32_t)((2 + s) * GST + lr * GSTR + lc) * 4u;
        #pragma unroll
        for (int i = 0; i < 4; i++) {
            cpa16(da + (uint32_t)(i * 32 * GSTR) * 4u, ap + (size_t)(i * 32) * K);
            cpa16(db + (uint32_t)(i * 32 * GSTR) * 4u, bp + (size_t)(i * 32) * K);
        }
        CP_COMMIT();
    };

    float acc[4][4][4] = {};
    issue(0, 0);

    for (int t = 0; t < KT; t++) {
        int s = t & 1;
        if (t + 1 < KT) { issue(t + 1, s ^ 1); CP_WAIT1(); } else { CP_WAIT0(); }
        __syncthreads();
        const float* As = sm + s * GST;
        const float* Bs = sm + (2 + s) * GST;

        #pragma unroll
        for (int ks = 0; ks < 4; ks++) {
            uint32_t af[4][4], bf[4][2];
            #pragma unroll
            for (int mi = 0; mi < 4; mi++) {
                const float* p = &As[(wm * 64 + mi * 16 + r) * GSTR + ks * 8 + c];
                af[mi][0] = __float_as_uint(p[0]);
                af[mi][1] = __float_as_uint(p[8 * GSTR]);
                af[mi][2] = __float_as_uint(p[4]);
                af[mi][3] = __float_as_uint(p[8 * GSTR + 4]);
            }
            #pragma unroll
            for (int ni = 0; ni < 4; ni++) {
                const float* p = &Bs[(wn * 32 + ni * 8 + r) * GSTR + ks * 8 + c];
                bf[ni][0] = __float_as_uint(p[0]);
                bf[ni][1] = __float_as_uint(p[4]);
            }
            #pragma unroll
            for (int mi = 0; mi < 4; mi++)
                #pragma unroll
                for (int ni = 0; ni < 4; ni++)
                    mma8(acc[mi][ni], af[mi], bf[ni]);
        }
        __syncthreads();
    }

    #pragma unroll
    for (int mi = 0; mi < 4; mi++) {
        int row = row0 + wm * 64 + mi * 16 + r;
        #pragma unroll
        for (int ni = 0; ni < 4; ni++) {
            int col = col0 + wn * 32 + ni * 8 + 2 * c;
            *(float2*)&C[(size_t)row * N + col] = make_float2(acc[mi][ni][0], acc[mi][ni][1]);
            *(float2*)&C[(size_t)(row + 8) * N + col] = make_float2(acc[mi][ni][2], acc[mi][ni][3]);
        }
    }
}

// ---------------------------------------------------------------------------
// QKV transform: RMSNorm q (D^-0.5 folded), k; scatter (tf32-rounded)
// ---------------------------------------------------------------------------
__global__ __launch_bounds__(256) void qkv_transform(
    const float* __restrict__ qg0, const float* __restrict__ kg0,
    const float* __restrict__ qg1, const float* __restrict__ kg1)
{
    int gw = (blockIdx.x * blockDim.x + threadIdx.x) >> 5;
    int lane = threadIdx.x & 31;
    int h = gw & (H - 1);
    int bn = gw >> 4;
    int n = bn & (NTOT - 1);
    int b = bn >> 11;

    const float *src, *qg, *kg;
    size_t rowoff;
    if (n < N0) { src = g_qkv0; rowoff = (size_t)(b * N0 + n) * (3 * DI); qg = qg0; kg = kg0; }
    else        { src = g_qkv1; rowoff = (size_t)(b * N1 + (n - N0)) * (3 * DI); qg = qg1; kg = kg1; }

    const float* qp = src + rowoff + h * DH;
    const float* kp = qp + DI;
    const float* vp = qp + 2 * DI;
    float q0 = qp[lane], q1 = qp[lane + 32];
    float k0 = kp[lane], k1 = kp[lane + 32];
    float v0 = vp[lane], v1 = vp[lane + 32];

    float qs = q0 * q0 + q1 * q1, ks = k0 * k0 + k1 * k1;
    #pragma unroll
    for (int off = 16; off; off >>= 1) {
        qs += __shfl_xor_sync(0xFFFFFFFFu, qs, off);
        ks += __shfl_xor_sync(0xFFFFFFFFu, ks, off);
    }
    float qinv = 1.0f / fmaxf(sqrtf(qs), 1e-12f);   // 8 * 0.125 = 1
    float kinv = 8.0f / fmaxf(sqrtf(ks), 1e-12f);

    size_t dst = ((size_t)(b * H + h) * NTOT + n) * DH;
    g_q[dst + lane]      = tf(q0 * qinv * qg[h * DH + lane]);
    g_q[dst + lane + 32] = tf(q1 * qinv * qg[h * DH + lane + 32]);
    g_k[dst + lane]      = tf(k0 * kinv * kg[h * DH + lane]);
    g_k[dst + lane + 32] = tf(k1 * kinv * kg[h * DH + lane + 32]);
    g_v[dst + lane]      = tf(v0);
    g_v[dst + lane + 32] = tf(v1);
}

// ---------------------------------------------------------------------------
// Attention (mma.sync flash, cp.async 2-stage K/VT). CTA = 128 q x one (b,h).
// 256 thr, 8 warps (16 q each), 32 key chunks of 64. Bounded logits.
// smem floats: Q @0 (128x68), K @8704 (2x64x68), VT @17408 (2x64x68),
//              P @26112 (128x68).  Total 34816 f = 139264 B.
// ---------------------------------------------------------------------------
#define ASTR 68
#define AQ  0
#define AK(s)  (8704 + (s) * 4352)
#define AV(s)  (17408 + (s) * 4352)
#define AP  26112
#define ATT_SMEM (34816 * 4)

__global__ __launch_bounds__(256) void attention_mma()
{
    extern __shared__ float sm[];
    uint32_t sbase = smem_u32(sm);
    int tid = threadIdx.x, lane = tid & 31, wid = tid >> 5;
    int wq = wid * 16;
    int bh = blockIdx.y;
    int q0 = blockIdx.x * 128;
    size_t base = (size_t)bh * NTOT * DH;
    const float* Vt = g_vt + (size_t)bh * DH * NTOT;
    int r = lane >> 2, c = lane & 3;

    int kvr = tid >> 2, kvc = (tid & 3) << 2;   // K/VT loads: 64 rows x 4 chunks/thr

    auto issueKV = [&](int kc, int s) {
        const float* kp = g_k + base + (size_t)(kc * 64 + kvr) * DH + kvc;
        const float* vp = Vt + (size_t)kvr * NTOT + kc * 64 + kvc;
        uint32_t dk = sbase + (uint32_t)(AK(s) + kvr * ASTR + kvc) * 4u;
        uint32_t dv = sbase + (uint32_t)(AV(s) + kvr * ASTR + kvc) * 4u;
        #pragma unroll
        for (int i = 0; i < 4; i++) {
            cpa16(dk + (uint32_t)(i * 16) * 4u, kp + i * 16);
            cpa16(dv + (uint32_t)(i * 16) * 4u, vp + i * 16);
        }
    };

    // group 0: Q tile + chunk 0
    {
        int qr = tid >> 1, qc = (tid & 1) << 2;
        const float* qp = g_q + base + (size_t)(q0 + qr) * DH + qc;
        uint32_t dq = sbase + (uint32_t)(AQ + qr * ASTR + qc) * 4u;
        #pragma unroll
        for (int i = 0; i < 8; i++)
            cpa16(dq + (uint32_t)(i * 8) * 4u, qp + i * 8);
        issueKV(0, 0);
        CP_COMMIT();
    }

    const float C1 = 72.134752f, C2 = -24.0449173f, C3 = 9.6179669f; // 50*log2e*{1,-1/3,2/15}
    float oacc[8][4] = {};
    float rs0 = 0.0f, rs1 = 0.0f;

    for (int kc = 0; kc < 32; kc++) {
        int s = kc & 1;
        if (kc + 1 < 32) { issueKV(kc + 1, s ^ 1); CP_COMMIT(); CP_WAIT1(); }
        else             { CP_WAIT0(); }
        __syncthreads();

        // S = Q K^T
        float sacc[8][4] = {};
        #pragma unroll
        for (int ks = 0; ks < 8; ks++) {
            uint32_t af[4];
            const float* pa = &sm[AQ + (wq + r) * ASTR + ks * 8 + c];
            af[0] = __float_as_uint(pa[0]);
            af[1] = __float_as_uint(pa[8 * ASTR]);
            af[2] = __float_as_uint(pa[4]);
            af[3] = __float_as_uint(pa[8 * ASTR + 4]);
            #pragma unroll
            for (int ni = 0; ni < 8; ni++) {
                uint32_t bf[2];
                const float* pb = &sm[AK(s) + (ni * 8 + r) * ASTR + ks * 8 + c];
                bf[0] = __float_as_uint(pb[0]);
                bf[1] = __float_as_uint(pb[4]);
                mma8(sacc[ni], af, bf);
            }
        }

        // softmax (softclamp poly + exp2) -> P smem (per-warp region)
        #pragma unroll
        for (int ni = 0; ni < 8; ni++) {
            float p[4];
            #pragma unroll
            for (int j = 0; j < 4; j++) {
                float x = sacc[ni][j] * 0.02f;
                float x2 = x * x;
                float u = x * fmaf(x2, fmaf(x2, C3, C2), C1);
                p[j] = ex2f(u);
            }
            rs0 += p[0] + p[1];
            rs1 += p[2] + p[3];
            *(float2*)&sm[AP + (wq + r) * ASTR + ni * 8 + 2 * c]     = make_float2(tf(p[0]), tf(p[1]));
            *(float2*)&sm[AP + (wq + r + 8) * ASTR + ni * 8 + 2 * c] = make_float2(tf(p[2]), tf(p[3]));
        }
        __syncwarp();

        // O += P V
        #pragma unroll
        for (int ks = 0; ks < 8; ks++) {
            uint32_t af[4];
            const float* pa = &sm[AP + (wq + r) * ASTR + ks * 8 + c];
            af[0] = __float_as_uint(pa[0]);
            af[1] = __float_as_uint(pa[8 * ASTR]);
            af[2] = __float_as_uint(pa[4]);
            af[3] = __float_as_uint(pa[8 * ASTR + 4]);
            #pragma unroll
            for (int ni = 0; ni < 8; ni++) {
                uint32_t bf[2];
                const float* pb = &sm[AV(s) + (ni * 8 + r) * ASTR + ks * 8 + c];
                bf[0] = __float_as_uint(pb[0]);
                bf[1] = __float_as_uint(pb[4]);
                mma8(oacc[ni], af, bf);
            }
        }
        __syncthreads();
    }

    rs0 += __shfl_xor_sync(0xFFFFFFFFu, rs0, 1);
    rs0 += __shfl_xor_sync(0xFFFFFFFFu, rs0, 2);
    rs1 += __shfl_xor_sync(0xFFFFFFFFu, rs1, 1);
    rs1 += __shfl_xor_sync(0xFFFFFFFFu, rs1, 2);
    float i0 = 1.0f / rs0, i1 = 1.0f / rs1;

    int b = bh >> 4, h = bh & (H - 1);
    int row = q0 + wq + r;
    float* op  = g_o + (size_t)(b * NTOT + row) * DI + h * DH;
    float* op8 = op + (size_t)8 * DI;
    #pragma unroll
    for (int ni = 0; ni < 8; ni++) {
        int col = ni * 8 + 2 * c;
        *(float2*)&op[col]  = make_float2(tf(oacc[ni][0] * i0), tf(oacc[ni][1] * i0));
        *(float2*)&op8[col] = make_float2(tf(oacc[ni][2] * i1), tf(oacc[ni][3] * i1));
    }
}

// ---------------------------------------------------------------------------
extern "C" void kernel_launch(void* const* d_in, const int* in_sizes, int n_in,
                              void* d_out, int out_size)
{
    const float* x0    = (const float*)d_in[0];
    const float* x1    = (const float*)d_in[1];
    const float* Wqkv0 = (const float*)d_in[2];
    const float* Wqkv1 = (const float*)d_in[3];
    const float* qg0   = (const float*)d_in[4];
    const float* kg0   = (const float*)d_in[5];
    const float* qg1   = (const float*)d_in[6];
    const float* kg1   = (const float*)d_in[7];
    const float* Wout0 = (const float*)d_in[8];
    const float* Wout1 = (const float*)d_in[9];
    float* out = (float*)d_out;

    float *qkv0, *qkv1, *o, *wt0, *wt1, *wtO0, *wtO1, *x0r, *x1r;
    cudaGetSymbolAddress((void**)&qkv0, g_qkv0);
    cudaGetSymbolAddress((void**)&qkv1, g_qkv1);
    cudaGetSymbolAddress((void**)&o,    g_o);
    cudaGetSymbolAddress((void**)&wt0,  g_wt0);
    cudaGetSymbolAddress((void**)&wt1,  g_wt1);
    cudaGetSymbolAddress((void**)&wtO0, g_wtO0);
    cudaGetSymbolAddress((void**)&wtO1, g_wtO1);
    cudaGetSymbolAddress((void**)&x0r,  g_x0r);
    cudaGetSymbolAddress((void**)&x1r,  g_x1r);

    cudaFuncSetAttribute(mma_gemm, cudaFuncAttributeMaxDynamicSharedMemorySize, GEMM_SMEM);
    cudaFuncSetAttribute(attention_mma, cudaFuncAttributeMaxDynamicSharedMemorySize, ATT_SMEM);

    dim3 t8(32, 8);
    round_tf<<<(B * N0 * D0) / 1024, 256>>>(x0, x0r);
    round_tf<<<(B * N1 * D1) / 1024, 256>>>(x1, x1r);
    transpose_k<<<dim3(3 * DI / 32, D0 / 32), t8>>>(Wqkv0, wt0, D0, 3 * DI);
    transpose_k<<<dim3(3 * DI / 32, D1 / 32), t8>>>(Wqkv1, wt1, D1, 3 * DI);
    transpose_k<<<dim3(D0 / 32, DI / 32), t8>>>(Wout0, wtO0, DI, D0);
    transpose_k<<<dim3(D1 / 32, DI / 32), t8>>>(Wout1, wtO1, DI, D1);

    mma_gemm<<<dim3(3 * DI / 128, B * N0 / 128), 256, GEMM_SMEM>>>(x0r, wt0, qkv0, B * N0, 3 * DI, D0);
    mma_gemm<<<dim3(3 * DI / 128, B * N1 / 128), 256, GEMM_SMEM>>>(x1r, wt1, qkv1, B * N1, 3 * DI, D1);

    qkv_transform<<<(B * NTOT * H) / 8, 256>>>(qg0, kg0, qg1, kg1);
    transpose_v<<<dim3(DH / 32, NTOT / 32, B * H), t8>>>();

    attention_mma<<<dim3(NTOT / 128, B * H), 256, ATT_SMEM>>>();

    float* out1 = out + (size_t)B * N0 * D0;
    for (int b = 0; b < B; b++) {
        mma_gemm<<<dim3(D0 / 128, N0 / 128), 256, GEMM_SMEM>>>(
            o + (size_t)b * NTOT * DI, wtO0, out + (size_t)b * N0 * D0, N0, D0, DI);
        mma_gemm<<<dim3(D1 / 128, N1 / 128), 256, GEMM_SMEM>>>(
            o + ((size_t)b * NTOT + N0) * DI, wtO1, out1 + (size_t)b * N1 * D1, N1, D1, DI);
    }
}